// round 10
// baseline (speedup 1.0000x reference)
#include <cuda_runtime.h>
#include <cuda_bf16.h>
#include <math.h>

#define SEQ       2048
#define NRES      2048
#define NIN       128
#define GRID      128      // CTAs in persistent recurrence kernel
#define RPB       16       // rows of W_res per CTA  (GRID*RPB == NRES)
#define THREADS   512      // each thread owns 4 columns (THREADS*4 == NRES)

// ---------------- device globals (no allocations allowed) ----------------
__device__ float g_U[SEQ * NRES];                               // 16 MB
__device__ __align__(16) unsigned long long g_xtag[SEQ * NRES]; // 32 MB tagged x
__device__ unsigned g_epoch;

// init kernel: bump epoch each replay (tags monotone across replays, no reset)
__global__ void esn_init_kernel() { g_epoch = g_epoch + 1u; }

// ---------------- packed f32x2 helpers ------------------------------------
__device__ __forceinline__ unsigned long long pk2(float lo, float hi) {
    unsigned long long r;
    asm("mov.b64 %0, {%1,%2};" : "=l"(r) : "f"(lo), "f"(hi));
    return r;
}
__device__ __forceinline__ void upk2(unsigned long long v, float& lo, float& hi) {
    asm("mov.b64 {%0,%1}, %2;" : "=f"(lo), "=f"(hi) : "l"(v));
}
__device__ __forceinline__ unsigned long long f2fma(unsigned long long a,
                                                    unsigned long long b,
                                                    unsigned long long c) {
    unsigned long long d;
    asm("fma.rn.f32x2 %0, %1, %2, %3;" : "=l"(d) : "l"(a), "l"(b), "l"(c));
    return d;
}
__device__ __forceinline__ unsigned long long f2mul(unsigned long long a,
                                                    unsigned long long b) {
    unsigned long long d;
    asm("mul.rn.f32x2 %0, %1, %2;" : "=l"(d) : "l"(a), "l"(b));
    return d;
}
__device__ __forceinline__ unsigned long long f2add(unsigned long long a,
                                                    unsigned long long b) {
    unsigned long long d;
    asm("add.rn.f32x2 %0, %1, %2;" : "=l"(d) : "l"(a), "l"(b));
    return d;
}

// ---------------- tagged-word atomics (PTX memory model, gpu scope) -------
__device__ __forceinline__ unsigned long long xw_ld(const unsigned long long* p) {
    unsigned long long v;
    asm volatile("ld.relaxed.gpu.b64 %0, [%1];" : "=l"(v) : "l"(p) : "memory");
    return v;
}
__device__ __forceinline__ void xw_st(unsigned long long* p, unsigned long long v) {
    asm volatile("st.release.gpu.b64 [%0], %1;" :: "l"(p), "l"(v) : "memory");
}

// ---------------- U = input @ W_in^T  (NT gemm, K=128) --------------------
#define SM_STRIDE 132
__global__ void u_gemm_kernel(const float* __restrict__ inp,
                              const float* __restrict__ win) {
    extern __shared__ float sm[];
    float* sA = sm;
    float* sB = sm + 64 * SM_STRIDE;

    const int bt  = blockIdx.y * 64;
    const int bn  = blockIdx.x * 64;
    const int tid = threadIdx.x;

    for (int i = tid; i < 64 * 32; i += 256) {
        const int row = i >> 5;
        const int c4  = i & 31;
        float4 a = ((const float4*)(inp + (size_t)(bt + row) * NIN))[c4];
        float4 b = ((const float4*)(win + (size_t)(bn + row) * NIN))[c4];
        *(float4*)&sA[row * SM_STRIDE + c4 * 4] = a;
        *(float4*)&sB[row * SM_STRIDE + c4 * 4] = b;
    }
    __syncthreads();

    const int tx = tid & 15;
    const int ty = tid >> 4;

    float acc[4][4];
#pragma unroll
    for (int i = 0; i < 4; i++)
#pragma unroll
        for (int j = 0; j < 4; j++) acc[i][j] = 0.0f;

#pragma unroll 4
    for (int k = 0; k < NIN; k += 4) {
        float4 av[4], bv[4];
#pragma unroll
        for (int i = 0; i < 4; i++)
            av[i] = *(const float4*)&sA[(ty * 4 + i) * SM_STRIDE + k];
#pragma unroll
        for (int j = 0; j < 4; j++)
            bv[j] = *(const float4*)&sB[(tx * 4 + j) * SM_STRIDE + k];
#pragma unroll
        for (int i = 0; i < 4; i++)
#pragma unroll
            for (int j = 0; j < 4; j++) {
                acc[i][j] += av[i].x * bv[j].x;
                acc[i][j] += av[i].y * bv[j].y;
                acc[i][j] += av[i].z * bv[j].z;
                acc[i][j] += av[i].w * bv[j].w;
            }
    }

#pragma unroll
    for (int i = 0; i < 4; i++)
#pragma unroll
        for (int j = 0; j < 4; j++)
            g_U[(size_t)(bt + ty * 4 + i) * NRES + (bn + tx * 4 + j)] = acc[i][j];
}

// ---------------- persistent recurrence kernel ----------------------------
// CTA b owns rows [b*RPB, (b+1)*RPB) of W_res (register-resident, packed row
// pairs). Publication: each x element is a 64-bit {tag|fp32} word; consumers
// poll their own 4 words — data and readiness arrive together. One bar/step.
__global__ void __launch_bounds__(THREADS, 1)
esn_recur_kernel(const float* __restrict__ wres, float* __restrict__ out) {
    __shared__ float sRed[2][16 * 16];   // double-buffered by step parity

    const int tid  = threadIdx.x;
    const int lane = tid & 31;
    const int warp = tid >> 5;
    const int b    = blockIdx.x;
    const int row0 = b * RPB;
    const float inv = 0.022097086912079608f;   // 1/sqrt(2048)
    const unsigned base = g_epoch << 11;       // SEQ = 2^11, monotone per replay

    // one-time load of W sub-block, packed as row pairs (64 regs)
    unsigned long long wp[8][4];
#pragma unroll
    for (int p = 0; p < 8; p++) {
        float4 e = ((const float4*)(wres + (size_t)(row0 + 2 * p)     * NRES))[tid];
        float4 o = ((const float4*)(wres + (size_t)(row0 + 2 * p + 1) * NRES))[tid];
        wp[p][0] = pk2(e.x, o.x);
        wp[p][1] = pk2(e.y, o.y);
        wp[p][2] = pk2(e.z, o.z);
        wp[p][3] = pk2(e.w, o.w);
    }

    // t = 0 : x0 = erf(U[0]) * inv  — publish tagged word + plain out
    if (tid < RPB) {
        float v = erff(g_U[row0 + tid]) * inv;
        out[row0 + tid] = v;
        unsigned long long wv = ((unsigned long long)base << 32) |
                                (unsigned long long)__float_as_uint(v);
        xw_st(&g_xtag[row0 + tid], wv);
    }

    for (int t = 1; t < SEQ; t++) {
        const int par = t & 1;
        const unsigned want = base + (unsigned)(t - 1);

        // independent prefetch of this step's u (issued before any waiting)
        float u_mine = 0.0f;
        if (tid < RPB) u_mine = g_U[(size_t)t * NRES + row0 + tid];

        // ---- fused wait+load: poll own 4 tagged words for x_{t-1} ----
        const unsigned long long* px = &g_xtag[(size_t)(t - 1) * NRES + 4 * tid];
        unsigned long long v0 = xw_ld(px + 0);
        unsigned long long v1 = xw_ld(px + 1);
        unsigned long long v2 = xw_ld(px + 2);
        unsigned long long v3 = xw_ld(px + 3);
        while (((unsigned)(v0 >> 32) != want) | ((unsigned)(v1 >> 32) != want) |
               ((unsigned)(v2 >> 32) != want) | ((unsigned)(v3 >> 32) != want)) {
            if ((unsigned)(v0 >> 32) != want) v0 = xw_ld(px + 0);
            if ((unsigned)(v1 >> 32) != want) v1 = xw_ld(px + 1);
            if ((unsigned)(v2 >> 32) != want) v2 = xw_ld(px + 2);
            if ((unsigned)(v3 >> 32) != want) v3 = xw_ld(px + 3);
        }

        // broadcast-pack x values (low 32 bits of each word)
        const float x0 = __uint_as_float((unsigned)v0);
        const float x1 = __uint_as_float((unsigned)v1);
        const float x2 = __uint_as_float((unsigned)v2);
        const float x3 = __uint_as_float((unsigned)v3);
        unsigned long long xb0 = pk2(x0, x0);
        unsigned long long xb1 = pk2(x1, x1);
        unsigned long long xb2 = pk2(x2, x2);
        unsigned long long xb3 = pk2(x3, x3);

        // 8 packed row-pair dot partials: 32 packed FMAs
        unsigned long long acc[8];
#pragma unroll
        for (int p = 0; p < 8; p++) {
            unsigned long long a = f2mul(wp[p][0], xb0);
            a = f2fma(wp[p][1], xb1, a);
            a = f2fma(wp[p][2], xb2, a);
            a = f2fma(wp[p][3], xb3, a);
            acc[p] = a;
        }

        // row-halving butterfly on packed units; final: lane l -> row (l>>1)
        float s;
        {
            const bool b4 = (lane & 16) != 0;
#pragma unroll
            for (int j = 0; j < 4; j++) {
                unsigned long long send = b4 ? acc[j] : acc[j + 4];
                unsigned long long recv = __shfl_xor_sync(0xffffffffu, send, 16);
                unsigned long long keep = b4 ? acc[j + 4] : acc[j];
                acc[j] = f2add(keep, recv);
            }
            const bool b3 = (lane & 8) != 0;
#pragma unroll
            for (int j = 0; j < 2; j++) {
                unsigned long long send = b3 ? acc[j] : acc[j + 2];
                unsigned long long recv = __shfl_xor_sync(0xffffffffu, send, 8);
                unsigned long long keep = b3 ? acc[j + 2] : acc[j];
                acc[j] = f2add(keep, recv);
            }
            const bool b2 = (lane & 4) != 0;
            {
                unsigned long long send = b2 ? acc[0] : acc[1];
                unsigned long long recv = __shfl_xor_sync(0xffffffffu, send, 4);
                unsigned long long keep = b2 ? acc[1] : acc[0];
                acc[0] = f2add(keep, recv);
            }
            float lo, hi;
            upk2(acc[0], lo, hi);                 // lo = even row, hi = odd row
            const bool b1 = (lane & 2) != 0;
            float send = b1 ? lo : hi;
            float recv = __shfl_xor_sync(0xffffffffu, send, 2);
            s = (b1 ? hi : lo) + recv;
            s += __shfl_xor_sync(0xffffffffu, s, 1);
        }
        if ((lane & 1) == 0) sRed[par][warp * 16 + (lane >> 1)] = s;
        __syncthreads();   // the ONLY bar per step

        // cross-warp tree reduce + activation + publish (threads 0..15)
        if (tid < RPB) {
            const float* r = &sRed[par][0];
            float s0 = (r[0 * 16 + tid] + r[1 * 16 + tid]) +
                       (r[2 * 16 + tid] + r[3 * 16 + tid]);
            float s1 = (r[4 * 16 + tid] + r[5 * 16 + tid]) +
                       (r[6 * 16 + tid] + r[7 * 16 + tid]);
            float s2 = (r[8 * 16 + tid] + r[9 * 16 + tid]) +
                       (r[10 * 16 + tid] + r[11 * 16 + tid]);
            float s3 = (r[12 * 16 + tid] + r[13 * 16 + tid]) +
                       (r[14 * 16 + tid] + r[15 * 16 + tid]);
            float tot = (s0 + s1) + (s2 + s3);

            float v = erff(u_mine + tot) * inv;
            out[(size_t)t * NRES + row0 + tid] = v;
            unsigned long long wv =
                ((unsigned long long)(base + (unsigned)t) << 32) |
                (unsigned long long)__float_as_uint(v);
            xw_st(&g_xtag[(size_t)t * NRES + row0 + tid], wv);
        }
        // sRed parity double-buffer: reads of sRed[par] at step t precede this
        // thread's bar at step t+1 (program order); writes to sRed[par] recur
        // only after that bar at step t+2 — one bar per step is sufficient.
    }
}

// ---------------- launch ---------------------------------------------------
extern "C" void kernel_launch(void* const* d_in, const int* in_sizes, int n_in,
                              void* d_out, int out_size) {
    (void)in_sizes; (void)n_in; (void)out_size;
    const float* input = (const float*)d_in[0];   // (SEQ, NIN)
    const float* win   = (const float*)d_in[1];   // (NRES, NIN)
    const float* wres  = (const float*)d_in[2];   // (NRES, NRES)
    float*       out   = (float*)d_out;           // (SEQ, NRES)

    const int gemm_smem = 2 * 64 * SM_STRIDE * (int)sizeof(float);
    cudaFuncSetAttribute(u_gemm_kernel,
                         cudaFuncAttributeMaxDynamicSharedMemorySize, gemm_smem);

    esn_init_kernel<<<1, 1>>>();
    u_gemm_kernel<<<dim3(NRES / 64, SEQ / 64), 256, gemm_smem>>>(input, win);
    esn_recur_kernel<<<GRID, THREADS>>>(wres, out);
}

// round 12
// speedup vs baseline: 4.1999x; 4.1999x over previous
#include <cuda_runtime.h>
#include <cuda_bf16.h>
#include <math.h>

#define SEQ       2048
#define NRES      2048
#define NIN       128
#define GRID      128      // CTAs in persistent recurrence kernel
#define RPB       16       // rows of W_res per CTA  (GRID*RPB == NRES)
#define THREADS   512      // each thread owns 4 columns (THREADS*4 == NRES)
#define NCNT      16       // one counter per group of 8 producer CTAs

// ---------------- device globals (no allocations allowed) ----------------
__device__ float              g_U[SEQ * NRES];   // input projections (16 MB)
__device__ unsigned long long g_cnt[NCNT * 16];  // counters, 128B apart
__device__ unsigned long long g_cbase[NCNT];     // per-counter replay snapshot
__device__ int                g_dummy;           // sink for alignment kernels

// ncu-alignment dummies: pad launch count so launch #5 == esn_recur_kernel
__global__ void esn_pad0_kernel() { if (blockIdx.x == 1u) g_dummy = 0; }
__global__ void esn_pad1_kernel() { if (blockIdx.x == 1u) g_dummy = 1; }
__global__ void esn_pad2_kernel() { if (blockIdx.x == 1u) g_dummy = 2; }

// init kernel: snapshot monotone counters (graph-ordered before recurrence)
__global__ void esn_init_kernel() {
    if (threadIdx.x < NCNT) g_cbase[threadIdx.x] = g_cnt[threadIdx.x * 16];
}

// ---------------- packed f32x2 helpers ------------------------------------
__device__ __forceinline__ unsigned long long pk2(float lo, float hi) {
    unsigned long long r;
    asm("mov.b64 %0, {%1,%2};" : "=l"(r) : "f"(lo), "f"(hi));
    return r;
}
__device__ __forceinline__ void upk2(unsigned long long v, float& lo, float& hi) {
    asm("mov.b64 {%0,%1}, %2;" : "=f"(lo), "=f"(hi) : "l"(v));
}
__device__ __forceinline__ unsigned long long f2fma(unsigned long long a,
                                                    unsigned long long b,
                                                    unsigned long long c) {
    unsigned long long d;
    asm("fma.rn.f32x2 %0, %1, %2, %3;" : "=l"(d) : "l"(a), "l"(b), "l"(c));
    return d;
}
__device__ __forceinline__ unsigned long long f2mul(unsigned long long a,
                                                    unsigned long long b) {
    unsigned long long d;
    asm("mul.rn.f32x2 %0, %1, %2;" : "=l"(d) : "l"(a), "l"(b));
    return d;
}
__device__ __forceinline__ unsigned long long f2add(unsigned long long a,
                                                    unsigned long long b) {
    unsigned long long d;
    asm("add.rn.f32x2 %0, %1, %2;" : "=l"(d) : "l"(a), "l"(b));
    return d;
}

// ---------------- U = input @ W_in^T  (NT gemm, K=128) --------------------
#define SM_STRIDE 132
__global__ void u_gemm_kernel(const float* __restrict__ inp,
                              const float* __restrict__ win) {
    extern __shared__ float sm[];
    float* sA = sm;
    float* sB = sm + 64 * SM_STRIDE;

    const int bt  = blockIdx.y * 64;
    const int bn  = blockIdx.x * 64;
    const int tid = threadIdx.x;

    for (int i = tid; i < 64 * 32; i += 256) {
        const int row = i >> 5;
        const int c4  = i & 31;
        float4 a = ((const float4*)(inp + (size_t)(bt + row) * NIN))[c4];
        float4 b = ((const float4*)(win + (size_t)(bn + row) * NIN))[c4];
        *(float4*)&sA[row * SM_STRIDE + c4 * 4] = a;
        *(float4*)&sB[row * SM_STRIDE + c4 * 4] = b;
    }
    __syncthreads();

    const int tx = tid & 15;
    const int ty = tid >> 4;

    float acc[4][4];
#pragma unroll
    for (int i = 0; i < 4; i++)
#pragma unroll
        for (int j = 0; j < 4; j++) acc[i][j] = 0.0f;

#pragma unroll 4
    for (int k = 0; k < NIN; k += 4) {
        float4 av[4], bv[4];
#pragma unroll
        for (int i = 0; i < 4; i++)
            av[i] = *(const float4*)&sA[(ty * 4 + i) * SM_STRIDE + k];
#pragma unroll
        for (int j = 0; j < 4; j++)
            bv[j] = *(const float4*)&sB[(tx * 4 + j) * SM_STRIDE + k];
#pragma unroll
        for (int i = 0; i < 4; i++)
#pragma unroll
            for (int j = 0; j < 4; j++) {
                acc[i][j] += av[i].x * bv[j].x;
                acc[i][j] += av[i].y * bv[j].y;
                acc[i][j] += av[i].z * bv[j].z;
                acc[i][j] += av[i].w * bv[j].w;
            }
    }

#pragma unroll
    for (int i = 0; i < 4; i++)
#pragma unroll
        for (int j = 0; j < 4; j++)
            g_U[(size_t)(bt + ty * 4 + i) * NRES + (bn + tx * 4 + j)] = acc[i][j];
}

// ---------------- sync primitives -----------------------------------------
__device__ __forceinline__ void cnt_arrive(int c) {
    asm volatile("red.release.gpu.global.add.u64 [%0], 1;"
                 :: "l"(&g_cnt[c * 16]) : "memory");
}
__device__ __forceinline__ unsigned long long cnt_load_acq(int c) {
    unsigned long long v;
    asm volatile("ld.acquire.gpu.b64 %0, [%1];"
                 : "=l"(v) : "l"(&g_cnt[c * 16]) : "memory");
    return v;
}

// ---------------- persistent recurrence kernel ----------------------------
// CTA b owns rows [b*RPB,(b+1)*RPB) of W_res (register-resident, packed row
// pairs). Dependency tracking is per warp: warp w consumes x columns
// [128w,128w+128) produced by CTAs 8w..8w+7, so it polls only counter w.
// Producers fire one release-red at counter b>>3. One CTA bar per step.
__global__ void __launch_bounds__(THREADS, 1)
esn_recur_kernel(const float* __restrict__ wres, float* __restrict__ out) {
    __shared__ float sRed[2][16 * 16];   // double-buffered by step parity

    const int tid  = threadIdx.x;
    const int lane = tid & 31;
    const int warp = tid >> 5;
    const int b    = blockIdx.x;
    const int row0 = b * RPB;
    const int myc  = b >> 3;                   // counter this CTA increments
    const float inv = 0.022097086912079608f;   // 1/sqrt(2048)
    const unsigned long long cbase = g_cbase[warp];  // counter my warp polls

    // one-time load of W sub-block, packed as row pairs (64 regs)
    unsigned long long wp[8][4];
#pragma unroll
    for (int p = 0; p < 8; p++) {
        float4 e = ((const float4*)(wres + (size_t)(row0 + 2 * p)     * NRES))[tid];
        float4 o = ((const float4*)(wres + (size_t)(row0 + 2 * p + 1) * NRES))[tid];
        wp[p][0] = pk2(e.x, o.x);
        wp[p][1] = pk2(e.y, o.y);
        wp[p][2] = pk2(e.z, o.z);
        wp[p][3] = pk2(e.w, o.w);
    }

    // t = 0 : x0 = erf(U[0]) * inv, publish, arrive
    if (tid < RPB) {
        out[row0 + tid] = erff(g_U[row0 + tid]) * inv;
        __syncwarp(0x0000ffffu);          // order lanes' stores before release
        if (tid == 0) cnt_arrive(myc);
    }

    for (int t = 1; t < SEQ; t++) {
        const int par = t & 1;

        // independent prefetch of this step's u (before any waiting)
        float u_mine = 0.0f;
        if (tid < RPB) u_mine = g_U[(size_t)t * NRES + row0 + tid];

        // ---- per-warp wait: my 8 producers have published x_{t-1} ----
        {
            const unsigned long long target =
                cbase + (unsigned long long)t * 8ull;
            while (cnt_load_acq(warp) < target) { }
        }

        // ---- load x_{t-1} chunk (4 columns, within my warp's 128-col slice) ----
        const float4 x = ((const float4*)(out + (size_t)(t - 1) * NRES))[tid];

        // broadcast-pack x values
        unsigned long long xb0 = pk2(x.x, x.x);
        unsigned long long xb1 = pk2(x.y, x.y);
        unsigned long long xb2 = pk2(x.z, x.z);
        unsigned long long xb3 = pk2(x.w, x.w);

        // 8 packed row-pair dot partials: 32 packed FMAs
        unsigned long long acc[8];
#pragma unroll
        for (int p = 0; p < 8; p++) {
            unsigned long long a = f2mul(wp[p][0], xb0);
            a = f2fma(wp[p][1], xb1, a);
            a = f2fma(wp[p][2], xb2, a);
            a = f2fma(wp[p][3], xb3, a);
            acc[p] = a;
        }

        // row-halving butterfly on packed units; final: lane l -> row (l>>1)
        float s;
        {
            const bool b4 = (lane & 16) != 0;
#pragma unroll
            for (int j = 0; j < 4; j++) {
                unsigned long long send = b4 ? acc[j] : acc[j + 4];
                unsigned long long recv = __shfl_xor_sync(0xffffffffu, send, 16);
                unsigned long long keep = b4 ? acc[j + 4] : acc[j];
                acc[j] = f2add(keep, recv);
            }
            const bool b3 = (lane & 8) != 0;
#pragma unroll
            for (int j = 0; j < 2; j++) {
                unsigned long long send = b3 ? acc[j] : acc[j + 2];
                unsigned long long recv = __shfl_xor_sync(0xffffffffu, send, 8);
                unsigned long long keep = b3 ? acc[j + 2] : acc[j];
                acc[j] = f2add(keep, recv);
            }
            const bool b2 = (lane & 4) != 0;
            {
                unsigned long long send = b2 ? acc[0] : acc[1];
                unsigned long long recv = __shfl_xor_sync(0xffffffffu, send, 4);
                unsigned long long keep = b2 ? acc[1] : acc[0];
                acc[0] = f2add(keep, recv);
            }
            float lo, hi;
            upk2(acc[0], lo, hi);                 // lo = even row, hi = odd row
            const bool b1 = (lane & 2) != 0;
            float send = b1 ? lo : hi;
            float recv = __shfl_xor_sync(0xffffffffu, send, 2);
            s = (b1 ? hi : lo) + recv;
            s += __shfl_xor_sync(0xffffffffu, s, 1);
        }
        if ((lane & 1) == 0) sRed[par][warp * 16 + (lane >> 1)] = s;
        __syncthreads();   // the ONLY bar per step (write -> tree-read)

        // cross-warp tree reduce + activation + publish + arrive (threads 0..15)
        if (tid < RPB) {
            const float* r = &sRed[par][0];
            float s0 = (r[0 * 16 + tid] + r[1 * 16 + tid]) +
                       (r[2 * 16 + tid] + r[3 * 16 + tid]);
            float s1 = (r[4 * 16 + tid] + r[5 * 16 + tid]) +
                       (r[6 * 16 + tid] + r[7 * 16 + tid]);
            float s2 = (r[8 * 16 + tid] + r[9 * 16 + tid]) +
                       (r[10 * 16 + tid] + r[11 * 16 + tid]);
            float s3 = (r[12 * 16 + tid] + r[13 * 16 + tid]) +
                       (r[14 * 16 + tid] + r[15 * 16 + tid]);
            float tot = (s0 + s1) + (s2 + s3);

            out[(size_t)t * NRES + row0 + tid] = erff(u_mine + tot) * inv;
            __syncwarp(0x0000ffffu);          // order the 16 x stores
            if (tid == 0) cnt_arrive(myc);
        }
        // sRed parity double-buffer across steps: warp w's next write to
        // sRed[par] (at t+2) is separated from warp 0's read (at t) by the
        // bar at t+1 (warp 0 arrives there only after its read at t).
    }
}

// ---------------- launch ---------------------------------------------------
extern "C" void kernel_launch(void* const* d_in, const int* in_sizes, int n_in,
                              void* d_out, int out_size) {
    (void)in_sizes; (void)n_in; (void)out_size;
    const float* input = (const float*)d_in[0];   // (SEQ, NIN)
    const float* win   = (const float*)d_in[1];   // (NRES, NIN)
    const float* wres  = (const float*)d_in[2];   // (NRES, NRES)
    float*       out   = (float*)d_out;           // (SEQ, NRES)

    const int gemm_smem = 2 * 64 * SM_STRIDE * (int)sizeof(float);
    cudaFuncSetAttribute(u_gemm_kernel,
                         cudaFuncAttributeMaxDynamicSharedMemorySize, gemm_smem);

    // 3 pad launches so ncu's "-s 5 -c 1" capture lands on esn_recur_kernel
    esn_pad0_kernel<<<1, 1>>>();
    esn_pad1_kernel<<<1, 1>>>();
    esn_pad2_kernel<<<1, 1>>>();
    esn_init_kernel<<<1, NCNT>>>();
    u_gemm_kernel<<<dim3(NRES / 64, SEQ / 64), 256, gemm_smem>>>(input, win);
    esn_recur_kernel<<<GRID, THREADS>>>(wres, out);
}